// round 4
// baseline (speedup 1.0000x reference)
#include <cuda_runtime.h>
#include <math.h>

#define L 256
#define D 300
#define S 16
#define KK 16
#define C 7
#define NS 48          // 3*S
#define DH 150         // D/2

// ---------------- scratch (device globals; no allocation) ----------------
__device__ float g_P0[L*D];
__device__ float g_P1[L*D];
__device__ float g_Q[L*D];
__device__ float g_Kb[L*D];
__device__ float g_Vb[L*D];
__device__ float g_hidden[L*D];
__device__ float g_A[L*D];
__device__ float g_relatt[L*D];
__device__ float g_norm[L];
__device__ float g_nodes[L*NS*D];   // 14.7 MB
__device__ int   g_nodemask[L*NS];
__device__ float g_sym[L*D];

__device__ __forceinline__ float warp_sum(float v) {
    #pragma unroll
    for (int o = 16; o; o >>= 1) v += __shfl_down_sync(0xffffffffu, v, o);
    return v;
}

// ---------------- K1: six GEMMs  out = utt @ W  (256x300x300 each) --------
__global__ void gemm6_kernel(const float* __restrict__ x,
                             const float* __restrict__ Wbasis,
                             const float* __restrict__ Wself,
                             const float* __restrict__ brgcn,
                             const float* __restrict__ Wq,
                             const float* __restrict__ Wk,
                             const float* __restrict__ Wv) {
    int l = blockIdx.x, m = blockIdx.y, j = threadIdx.x;
    __shared__ float xs[D];
    for (int i = threadIdx.x; i < D; i += blockDim.x) xs[i] = x[l*D + i];
    __syncthreads();
    if (j >= D) return;
    const float* W; float* out;
    switch (m) {
        case 0: W = Wbasis;        out = g_P0;     break;
        case 1: W = Wbasis + D*D;  out = g_P1;     break;
        case 2: W = Wself;         out = g_hidden; break;
        case 3: W = Wq;            out = g_Q;      break;
        case 4: W = Wk;            out = g_Kb;     break;
        default:W = Wv;            out = g_Vb;     break;
    }
    float acc = 0.f;
    #pragma unroll 4
    for (int k = 0; k < D; k++) acc = fmaf(xs[k], W[k*D + j], acc);
    if (m == 2) acc += brgcn[j];
    out[l*D + j] = acc;
}

// ---------------- K2: RGCN edge scatter via basis decomposition ----------
__global__ void edge_kernel(const int* __restrict__ src,
                            const int* __restrict__ dst,
                            const int* __restrict__ etype,
                            const float* __restrict__ comp) {
    int e = blockIdx.x, j = threadIdx.x;
    if (j >= D) return;
    int r = etype[e];
    float c0 = comp[2*r], c1 = comp[2*r + 1];
    int s = src[e], d = dst[e];
    float v = c0 * g_P0[s*D + j] + c1 * g_P1[s*D + j];
    atomicAdd(&g_hidden[d*D + j], v);
}

// ---------------- K3: windowed 2-head attention (only center query) ------
__global__ void attn_kernel() {
    int l = blockIdx.x;
    int tid = threadIdx.x, warp = tid >> 5, lane = tid & 31;
    __shared__ float lg[2][3];
    __shared__ float p[2][3];
    int w0 = (l == 0) ? 0 : l - 1;
    int w2 = (l == L-1) ? L-1 : l + 1;
    int win[3] = {w0, l, w2};
    if (warp < 6) {
        int h = warp / 3, j = warp % 3;
        const float* q = g_Q  + l*D       + h*DH;
        const float* k = g_Kb + win[j]*D  + h*DH;
        float acc = 0.f;
        for (int d = lane; d < DH; d += 32) acc += q[d] * k[d];
        acc = warp_sum(acc);
        if (lane == 0) lg[h][j] = acc * 0.08164965809277261f;  // 1/sqrt(150)
    }
    __syncthreads();
    if (tid < 2) {
        float m = fmaxf(lg[tid][0], fmaxf(lg[tid][1], lg[tid][2]));
        float e0 = expf(lg[tid][0]-m), e1 = expf(lg[tid][1]-m), e2 = expf(lg[tid][2]-m);
        float inv = 1.f / (e0 + e1 + e2);
        p[tid][0] = e0*inv; p[tid][1] = e1*inv; p[tid][2] = e2*inv;
    }
    __syncthreads();
    for (int t = tid; t < D; t += blockDim.x) {
        int h = t / DH, d = t - h*DH;
        float acc = p[h][0] * g_Vb[win[0]*D + h*DH + d]
                  + p[h][1] * g_Vb[win[1]*D + h*DH + d]
                  + p[h][2] * g_Vb[win[2]*D + h*DH + d];
        g_A[l*D + t] = acc;
    }
}

// ---------------- K4: relatt = A @ Wo, plus row norms --------------------
__global__ void wo_kernel(const float* __restrict__ Wo) {
    int l = blockIdx.x, tid = threadIdx.x;
    __shared__ float xs[D];
    __shared__ float red[10];
    for (int i = tid; i < D; i += blockDim.x) xs[i] = g_A[l*D + i];
    __syncthreads();
    float out = 0.f;
    if (tid < D) {
        #pragma unroll 4
        for (int k = 0; k < D; k++) out = fmaf(xs[k], Wo[k*D + tid], out);
        g_relatt[l*D + tid] = out;
    }
    float sq = (tid < D) ? out * out : 0.f;
    sq = warp_sum(sq);
    int warp = tid >> 5, lane = tid & 31;
    if (lane == 0) red[warp] = sq;
    __syncthreads();
    if (tid == 0) {
        float t = 0.f;
        #pragma unroll
        for (int w = 0; w < 10; w++) t += red[w];
        g_norm[l] = sqrtf(t);
    }
}

// ---------------- K5: concept-graph attention (the big gather) -----------
// one block per (g, l, s). Load each dst row ONCE into shared; compute all
// three dots in that pass; two tiny softmaxes; epilogue from shared.
__global__ void concept_kernel(const int* __restrict__ src_ids,
                               const int* __restrict__ dst_ids,
                               const float* __restrict__ wgt,
                               const float* __restrict__ sentic,
                               const float* __restrict__ table,
                               const float* __restrict__ rvecs) {
    int bid = blockIdx.x;                 // g*L*S + l*S + s
    int g = bid / (L*S);
    int rem = bid - g*(L*S);
    int l = rem / S;
    int s = rem - l*S;
    int n = g*S + s;                      // node index within row l
    int tid = threadIdx.x;                // 256 threads, 8 warps

    __shared__ float sh_dst[KK][D];
    __shared__ float sh_src[D], sh_u[D], sh_r[D];
    __shared__ float sh_du[KK], sh_dd[KK], sh_ds[KK], sh_c[KK];
    __shared__ int   sh_ids[KK];

    int src_id = src_ids[bid];
    float* outrow = &g_nodes[(size_t)(l*NS + n) * D];
    if (src_id < 0) {
        if (tid == 0) g_nodemask[l*NS + n] = 0;
        for (int d = tid; d < D; d += 256) outrow[d] = 0.f;
        return;
    }
    if (tid == 0) g_nodemask[l*NS + n] = 1;
    if (tid < KK) sh_ids[tid] = dst_ids[(size_t)bid*KK + tid];
    for (int d = tid; d < D; d += 256) {
        sh_src[d] = table[(size_t)src_id*D + d];
        sh_u[d]   = g_relatt[l*D + d];
        sh_r[d]   = rvecs[g*D + d];
    }
    __syncthreads();

    int warp = tid >> 5, lane = tid & 31;
    #pragma unroll
    for (int kit = 0; kit < 2; kit++) {
        int k = warp + kit*8;
        int id = sh_ids[k];
        float du = 0.f, dd = 0.f, ds = 0.f;
        if (id >= 0) {
            const float* row = table + (size_t)id*D;
            for (int d = lane; d < D; d += 32) {
                float v = row[d];
                sh_dst[k][d] = v;
                du = fmaf(sh_u[d], v, du);
                dd = fmaf(v, v, dd);
                ds = fmaf(sh_src[d]*sh_r[d], v, ds);
            }
            du = warp_sum(du); dd = warp_sum(dd); ds = warp_sum(ds);
        } else {
            for (int d = lane; d < D; d += 32) sh_dst[k][d] = 0.f;
        }
        if (lane == 0) { sh_du[k] = du; sh_dd[k] = dd; sh_ds[k] = ds; }
    }
    __syncthreads();

    if (tid == 0) {
        float norm_u = g_norm[l];
        float om[KK], a1[KK], sv[KK], a2[KK];
        float m1 = -1e30f; int anyv = 0;
        for (int k = 0; k < KK; k++) {
            if (sh_ids[k] >= 0) {
                float cosv = fabsf(sh_du[k]) / (norm_u * sqrtf(sh_dd[k]) + 1e-8f);
                float w  = wgt[(size_t)bid*KK + k];
                float sn = sentic[(size_t)bid*KK + k];
                om[k] = 0.5f*w*cosv + 0.5f*fabsf(sn);
                if (om[k] > m1) m1 = om[k];
                anyv = 1;
            } else om[k] = 0.f;
        }
        float sum1 = 0.f;
        for (int k = 0; k < KK; k++) {
            a1[k] = (sh_ids[k] >= 0) ? expf(om[k] - m1) : 0.f;
            sum1 += a1[k];
        }
        float inv1 = anyv ? (1.f / sum1) : 0.f;
        float m2 = -1e30f;
        for (int k = 0; k < KK; k++) {
            a1[k] *= inv1;
            sv[k] = a1[k] * sh_ds[k];
            if (sh_ids[k] >= 0 && sv[k] > m2) m2 = sv[k];
        }
        float sum2 = 0.f;
        for (int k = 0; k < KK; k++) {
            a2[k] = (sh_ids[k] >= 0) ? expf(sv[k] - m2) : 0.f;
            sum2 += a2[k];
        }
        float inv2 = anyv ? (1.f / sum2) : 0.f;
        for (int k = 0; k < KK; k++) sh_c[k] = a1[k] * a2[k] * inv2;
    }
    __syncthreads();

    for (int d = tid; d < D; d += 256) {
        float acc = 0.f;
        #pragma unroll
        for (int k = 0; k < KK; k++) acc = fmaf(sh_c[k], sh_dst[k][d], acc);
        outrow[d] = sh_src[d] + sh_r[d] * acc;
    }
}

// ---------------- K6: symbolic attention over 48 nodes -------------------
__global__ void sym_kernel() {
    int l = blockIdx.x, tid = threadIdx.x;   // 256 threads
    __shared__ float sh_u[D];
    __shared__ float score[NS];
    __shared__ float att[NS];
    __shared__ float s_any;
    for (int d = tid; d < D; d += 256) sh_u[d] = g_relatt[l*D + d];
    __syncthreads();
    int warp = tid >> 5, lane = tid & 31;
    #pragma unroll
    for (int it = 0; it < 6; it++) {
        int nn = warp + it*8;
        float acc = 0.f;
        if (g_nodemask[l*NS + nn]) {
            const float* row = &g_nodes[(size_t)(l*NS + nn) * D];
            for (int d = lane; d < D; d += 32) acc = fmaf(row[d], sh_u[d], acc);
            acc = warp_sum(acc);
        }
        if (lane == 0) score[nn] = acc;
    }
    __syncthreads();
    if (tid == 0) {
        float m = -1e30f; int anyv = 0;
        for (int nn = 0; nn < NS; nn++)
            if (g_nodemask[l*NS + nn]) { if (score[nn] > m) m = score[nn]; anyv = 1; }
        float sum = 0.f;
        for (int nn = 0; nn < NS; nn++) {
            att[nn] = g_nodemask[l*NS + nn] ? expf(score[nn] - m) : 0.f;
            sum += att[nn];
        }
        float inv = anyv ? (1.f / sum) : 0.f;
        for (int nn = 0; nn < NS; nn++) att[nn] *= inv;
        s_any = anyv ? 1.f : 0.f;
    }
    __syncthreads();
    for (int d = tid; d < D; d += 256) {
        float acc = 0.f;
        for (int nn = 0; nn < NS; nn++)
            acc = fmaf(att[nn], g_nodes[(size_t)(l*NS + nn) * D + d], acc);
        g_sym[l*D + d] = acc * s_any;
    }
}

// ---------------- K7: fuse MLP + log_softmax -----------------------------
__global__ void fuse_kernel(const float* __restrict__ Wf,
                            const float* __restrict__ bf,
                            const float* __restrict__ Wout,
                            const float* __restrict__ bout,
                            float* __restrict__ out) {
    int l = blockIdx.x, tid = threadIdx.x;   // 320 threads
    __shared__ float feat[3*D];
    __shared__ float h1[D];
    __shared__ float logits[C];
    __shared__ float sh_lse;
    for (int i = tid; i < D; i += blockDim.x) {
        feat[i]       = g_hidden[l*D + i];
        feat[D + i]   = g_relatt[l*D + i];
        feat[2*D + i] = g_sym[l*D + i];
    }
    __syncthreads();
    if (tid < D) {
        float acc = bf[tid];
        #pragma unroll 4
        for (int i = 0; i < 3*D; i++) acc = fmaf(feat[i], Wf[i*D + tid], acc);
        h1[tid] = fmaxf(acc, 0.f);
    }
    __syncthreads();
    int warp = tid >> 5, lane = tid & 31;
    if (warp < C) {
        float acc = 0.f;
        for (int j = lane; j < D; j += 32) acc = fmaf(h1[j], Wout[j*C + warp], acc);
        acc = warp_sum(acc);
        if (lane == 0) logits[warp] = acc + bout[warp];
    }
    __syncthreads();
    if (tid == 0) {
        float m = logits[0];
        #pragma unroll
        for (int c = 1; c < C; c++) m = fmaxf(m, logits[c]);
        float sum = 0.f;
        #pragma unroll
        for (int c = 0; c < C; c++) sum += expf(logits[c] - m);
        sh_lse = m + logf(sum);
    }
    __syncthreads();
    if (tid < C) out[l*C + tid] = logits[tid] - sh_lse;
}

// ---------------- launch --------------------------------------------------
extern "C" void kernel_launch(void* const* d_in, const int* in_sizes, int n_in,
                              void* d_out, int out_size) {
    const float* utt    = (const float*)d_in[0];
    const int*   ssrc   = (const int*)  d_in[1];
    const int*   sdst   = (const int*)  d_in[2];
    const int*   setype = (const int*)  d_in[3];
    const int*   csrc   = (const int*)  d_in[4];
    const int*   cdst   = (const int*)  d_in[5];
    const float* cw     = (const float*)d_in[6];
    const float* cs     = (const float*)d_in[7];
    const float* table  = (const float*)d_in[8];
    const float* Wbasis = (const float*)d_in[9];
    const float* comp   = (const float*)d_in[10];
    const float* Wself  = (const float*)d_in[11];
    const float* brgcn  = (const float*)d_in[12];
    const float* Wq     = (const float*)d_in[13];
    const float* Wk     = (const float*)d_in[14];
    const float* Wv     = (const float*)d_in[15];
    const float* Wo     = (const float*)d_in[16];
    const float* rvecs  = (const float*)d_in[17];
    const float* Wf     = (const float*)d_in[18];
    const float* bf     = (const float*)d_in[19];
    const float* Wout   = (const float*)d_in[20];
    const float* bout   = (const float*)d_in[21];
    float* out = (float*)d_out;

    int n_edges = in_sizes[1];

    gemm6_kernel<<<dim3(L, 6), 320>>>(utt, Wbasis, Wself, brgcn, Wq, Wk, Wv);
    edge_kernel<<<n_edges, 320>>>(ssrc, sdst, setype, comp);
    attn_kernel<<<L, 192>>>();
    wo_kernel<<<L, 320>>>(Wo);
    concept_kernel<<<3*L*S, 256>>>(csrc, cdst, cw, cs, table, rvecs);
    sym_kernel<<<L, 256>>>();
    fuse_kernel<<<L, 320>>>(Wf, bf, Wout, bout, out);
}